// round 7
// baseline (speedup 1.0000x reference)
#include <cuda_runtime.h>

// PCEN: M = EMA(data, s=0.5) along T;  out = (x/(eps+M)^alpha + delta)^r - delta^r
// data: [F=1024, T=50000] fp32 row-major. alpha/r/delta: 1-elem fp32 arrays.
//
// R7: register-only formulation. Each lane owns ONE float4 (coalesced LDG/STG).
// EMA over a float4 is affine: M -> M/16 + W, W = sum_e 0.5^(4-e) x_e.
// Decayed Kogge-Stone scan (shfl.up shifts 1,2,4; factors 16^-1,16^-2,16^-4)
// gives S_l = sum_{k=0..7} W_{l-k} 16^-k; M_start(l) = S_{l-1} == the exact
// 32-sample truncated EMA window (0.5^32 tail ~ 2.3e-10; gate 1e-3).
// Lanes 0-7 are halo (load the 32 floats before the warp's span, no output);
// lanes 8-31 each produce one float4. No smem, no __syncthreads.

#define BLOCK        256
#define WARPS        (BLOCK / 32)
#define OUT_PER_WARP 24                      // float4 outputs (lanes 8..31)
#define OUT_PER_BLK  (WARPS * OUT_PER_WARP)  // 192 float4 per block

__device__ __forceinline__ float ex2a(float x)  { float y; asm("ex2.approx.f32 %0, %1;"  : "=f"(y) : "f"(x)); return y; }
__device__ __forceinline__ float lg2a(float x)  { float y; asm("lg2.approx.f32 %0, %1;"  : "=f"(y) : "f"(x)); return y; }
__device__ __forceinline__ float sqrta(float x) { float y; asm("sqrt.approx.f32 %0, %1;" : "=f"(y) : "f"(x)); return y; }

__device__ __forceinline__ float pcen_g(float x, float& M, float alpha,
                                        float r, float delta, float dr)
{
    M = 0.5f * (M + x);
    const float inv = ex2a(-alpha * lg2a(M + 1e-6f));
    const float y   = fmaf(x, inv, delta);
    return ex2a(r * lg2a(y)) - dr;
}

__device__ __forceinline__ float pcen_h(float x, float& M, float alpha,
                                        float delta, float dr)
{
    M = 0.5f * (M + x);
    const float inv = ex2a(-alpha * lg2a(M + 1e-6f));
    const float y   = fmaf(x, inv, delta);
    return sqrta(y) - dr;
}

__global__ __launch_bounds__(BLOCK)
void pcen_kernel(const float4* __restrict__ data4,
                 const float*  __restrict__ alpha_p,
                 const float*  __restrict__ r_p,
                 const float*  __restrict__ delta_p,
                 float4* __restrict__ out4,
                 int T4)                              // T/4 = 12500
{
    const int lane = threadIdx.x & 31;
    const int wrp  = threadIdx.x >> 5;
    const int rowBase4 = blockIdx.y * T4;             // < 12.8M, int32 ok

    // lane l handles float4 index q; lanes 0-7 are the 8-float4 (32-sample) halo
    const int q = blockIdx.x * OUT_PER_BLK + wrp * OUT_PER_WARP + lane - 8;

    // ---- coalesced load (zero outside row: matches zero-init EMA state) ----
    float4 x = make_float4(0.f, 0.f, 0.f, 0.f);
    if (q >= 0 && q < T4) x = data4[rowBase4 + q];

    // ---- per-lane affine term: W = x0/16 + x1/8 + x2/4 + x3/2 ----
    float W = x.w * 0.5f;
    W = fmaf(x.z, 0.25f,   W);
    W = fmaf(x.y, 0.125f,  W);
    W = fmaf(x.x, 0.0625f, W);

    // ---- decayed inclusive scan over lanes (coverage: 8 lanes = 32 samples) ----
    float S = W;
    float t;
    t = __shfl_up_sync(0xffffffffu, S, 1); if (lane >= 1) S = fmaf(t, 0.0625f,              S);
    t = __shfl_up_sync(0xffffffffu, S, 2); if (lane >= 2) S = fmaf(t, 3.90625e-3f,          S);
    t = __shfl_up_sync(0xffffffffu, S, 4); if (lane >= 4) S = fmaf(t, 1.52587890625e-5f,    S);

    // state entering this lane's 4 samples
    float M = __shfl_up_sync(0xffffffffu, S, 1);      // lane 0 value unused

    // ---- lanes 8-31: run exact 4-step recurrence + PCEN, coalesced store ----
    if (lane >= 8 && q < T4) {
        const float alpha = *alpha_p;
        const float r     = *r_p;
        const float delta = *delta_p;

        float4 res;
        if (r == 0.5f) {
            const float dr = sqrta(delta);
            res.x = pcen_h(x.x, M, alpha, delta, dr);
            res.y = pcen_h(x.y, M, alpha, delta, dr);
            res.z = pcen_h(x.z, M, alpha, delta, dr);
            res.w = pcen_h(x.w, M, alpha, delta, dr);
        } else {
            const float dr = ex2a(r * lg2a(delta));
            res.x = pcen_g(x.x, M, alpha, r, delta, dr);
            res.y = pcen_g(x.y, M, alpha, r, delta, dr);
            res.z = pcen_g(x.z, M, alpha, r, delta, dr);
            res.w = pcen_g(x.w, M, alpha, r, delta, dr);
        }
        out4[rowBase4 + q] = res;
    }
}

extern "C" void kernel_launch(void* const* d_in, const int* in_sizes, int n_in,
                              void* d_out, int out_size)
{
    const float4* data4   = (const float4*)d_in[0];
    const float*  alpha_p = (const float*)d_in[1];
    const float*  r_p     = (const float*)d_in[2];
    const float*  delta_p = (const float*)d_in[3];
    float4* out4 = (float4*)d_out;

    const int total = in_sizes[0];
    const int F = 1024;
    const int T  = total / F;                          // 50000
    const int T4 = T / 4;                              // 12500
    const int blocksPerRow = (T4 + OUT_PER_BLK - 1) / OUT_PER_BLK;  // 66

    dim3 grid(blocksPerRow, F);
    pcen_kernel<<<grid, BLOCK>>>(data4, alpha_p, r_p, delta_p, out4, T4);
}

// round 8
// speedup vs baseline: 1.3777x; 1.3777x over previous
#include <cuda_runtime.h>

// PCEN: M = EMA(data, s=0.5) along T;  out = (x/(eps+M)^alpha + delta)^r - delta^r
// data: [F=1024, T=50000] fp32 row-major. alpha/r/delta: 1-elem fp32 arrays.
//
// R8: register-only decayed warp-scan with cross-iteration carry.
// Warp segment = 8 iterations x 32 lanes x 1 float4 (coalesced, idx = base+k*32+lane).
// Per float4 the EMA is affine: M -> M/16 + W, W = sum_e 0.5^(4-e) x_e.
// Truncated Kogge-Stone (shifts 1,2,4; lambda=1/16) gives 8-float4 (=32-sample)
// coverage; cross-k carry = S(lane31), injected as carry*16^-lane. Truncation
// tail 0.5^32 ~ 2.3e-10 (gate 1e-3). Halo: ONE predicated float4 on lanes
// 24-31 (3% read overhead). All 9 loads issued up front (MLP=9). No smem.

#define BLOCK  256
#define WARPS  (BLOCK / 32)
#define KITER  8
#define SEG4   (KITER * 32)          // 256 float4 per warp segment

__device__ __forceinline__ float ex2a(float x)  { float y; asm("ex2.approx.f32 %0, %1;"  : "=f"(y) : "f"(x)); return y; }
__device__ __forceinline__ float lg2a(float x)  { float y; asm("lg2.approx.f32 %0, %1;"  : "=f"(y) : "f"(x)); return y; }
__device__ __forceinline__ float sqrta(float x) { float y; asm("sqrt.approx.f32 %0, %1;" : "=f"(y) : "f"(x)); return y; }

__device__ __forceinline__ float pcen_g(float x, float& M, float alpha,
                                        float r, float delta, float dr)
{
    M = 0.5f * (M + x);
    const float inv = ex2a(-alpha * lg2a(M + 1e-6f));
    const float y   = fmaf(x, inv, delta);
    return ex2a(r * lg2a(y)) - dr;
}

__device__ __forceinline__ float pcen_h(float x, float& M, float alpha,
                                        float delta, float dr)
{
    M = 0.5f * (M + x);
    const float inv = ex2a(-alpha * lg2a(M + 1e-6f));
    const float y   = fmaf(x, inv, delta);
    return sqrta(y) - dr;
}

// per-lane affine term of one float4: W = x0/16 + x1/8 + x2/4 + x3/2
__device__ __forceinline__ float wterm(const float4& x)
{
    float W = x.w * 0.5f;
    W = fmaf(x.z, 0.25f,   W);
    W = fmaf(x.y, 0.125f,  W);
    W = fmaf(x.x, 0.0625f, W);
    return W;
}

// truncated decayed inclusive scan, lambda = 1/16, coverage 8 lanes
__device__ __forceinline__ float dscan(float W, int lane)
{
    float S = W, t;
    t = __shfl_up_sync(0xffffffffu, S, 1); if (lane >= 1) S = fmaf(t, 0.0625f,           S);
    t = __shfl_up_sync(0xffffffffu, S, 2); if (lane >= 2) S = fmaf(t, 3.90625e-3f,       S);
    t = __shfl_up_sync(0xffffffffu, S, 4); if (lane >= 4) S = fmaf(t, 1.52587890625e-5f, S);
    return S;
}

__global__ __launch_bounds__(BLOCK)
void pcen_kernel(const float4* __restrict__ data4,
                 const float*  __restrict__ alpha_p,
                 const float*  __restrict__ r_p,
                 const float*  __restrict__ delta_p,
                 float4* __restrict__ out4,
                 int T4)                               // T/4 = 12500
{
    const int lane = threadIdx.x & 31;
    const int wrp  = threadIdx.x >> 5;
    const int rowBase4 = blockIdx.y * T4;              // int32 safe (<12.8M)
    const int base4 = (blockIdx.x * WARPS + wrp) * SEG4;

    if (base4 >= T4) return;                           // warp-uniform exit

    // ---- issue all loads up front (MLP = 9) ----
    float4 x[KITER];
    #pragma unroll
    for (int k = 0; k < KITER; ++k) {
        const int idx = base4 + k * 32 + lane;
        x[k] = make_float4(0.f, 0.f, 0.f, 0.f);
        if (idx < T4) x[k] = data4[rowBase4 + idx];
    }
    float4 h = make_float4(0.f, 0.f, 0.f, 0.f);
    {
        const int hidx = base4 - 32 + lane;            // lanes 24..31 = last 8 float4s before seg
        if (lane >= 24 && hidx >= 0) h = data4[rowBase4 + hidx];
    }

    const float alpha = *alpha_p;
    const float r     = *r_p;
    const float delta = *delta_p;
    const bool  rhalf = (r == 0.5f);
    const float dr    = rhalf ? sqrta(delta) : ex2a(r * lg2a(delta));

    // 16^-lane as exponent bits (lane<=31 -> exp >= 3, representable)
    const float fl = __uint_as_float((unsigned)(127 - 4 * lane) << 23);

    // ---- halo: carry entering k=0 (lanes <24 contribute 0) ----
    float carry = __shfl_sync(0xffffffffu, dscan(wterm(h), lane), 31);

    // ---- 8 iterations: scan + carry + element math + coalesced store ----
    #pragma unroll
    for (int k = 0; k < KITER; ++k) {
        const float S = dscan(wterm(x[k]), lane);
        const float t = __shfl_up_sync(0xffffffffu, S, 1);
        float M = fmaf(carry, fl, (lane != 0) ? t : 0.0f);   // state entering this float4
        carry = __shfl_sync(0xffffffffu, S, 31);             // next-k carry (old*16^-32 ~ 0)

        float4 res;
        if (rhalf) {
            res.x = pcen_h(x[k].x, M, alpha, delta, dr);
            res.y = pcen_h(x[k].y, M, alpha, delta, dr);
            res.z = pcen_h(x[k].z, M, alpha, delta, dr);
            res.w = pcen_h(x[k].w, M, alpha, delta, dr);
        } else {
            res.x = pcen_g(x[k].x, M, alpha, r, delta, dr);
            res.y = pcen_g(x[k].y, M, alpha, r, delta, dr);
            res.z = pcen_g(x[k].z, M, alpha, r, delta, dr);
            res.w = pcen_g(x[k].w, M, alpha, r, delta, dr);
        }

        const int idx = base4 + k * 32 + lane;
        if (idx < T4) out4[rowBase4 + idx] = res;
    }
}

extern "C" void kernel_launch(void* const* d_in, const int* in_sizes, int n_in,
                              void* d_out, int out_size)
{
    const float4* data4   = (const float4*)d_in[0];
    const float*  alpha_p = (const float*)d_in[1];
    const float*  r_p     = (const float*)d_in[2];
    const float*  delta_p = (const float*)d_in[3];
    float4* out4 = (float4*)d_out;

    const int total = in_sizes[0];
    const int F = 1024;
    const int T  = total / F;                           // 50000
    const int T4 = T / 4;                               // 12500
    const int segsPerRow   = (T4 + SEG4 - 1) / SEG4;    // 49
    const int blocksPerRow = (segsPerRow + WARPS - 1) / WARPS;  // 7

    dim3 grid(blocksPerRow, F);
    pcen_kernel<<<grid, BLOCK>>>(data4, alpha_p, r_p, delta_p, out4, T4);
}